// round 6
// baseline (speedup 1.0000x reference)
#include <cuda_runtime.h>
#include <math.h>
#include <stdint.h>

#define DIMC   512
#define NHEADS 8
#define DHD    64
#define NDEPTH 2
#define BBATCH 2
#define NSEQ   1024
#define DINNER 512
#define FFD    2048
#define MTOK   (BBATCH*NSEQ)
#define EPSV   1e-6f
#define SCALEV 0.125f

#define EP_NONE   0
#define EP_ROPE   1
#define EP_ROPE_K 2
#define EP_NONLIN 3   // magnitude nonlinearity + tf32-round (W1 output feeds W2's A)

// ---------------- scratch ---------------------------------------------------
__device__ float2 g_x [MTOK*DIMC];
__device__ float2 g_h [MTOK*DIMC];
__device__ float2 g_q [MTOK*DINNER];
__device__ float2 g_kv[MTOK*2*DINNER];
__device__ float  g_o4[4*BBATCH*NHEADS*NSEQ*DHD];
__device__ float2 g_oc[MTOK*DINNER];
__device__ float2 g_h1[MTOK*FFD];
__device__ float  g_cos[NSEQ*DHD];
__device__ float  g_sin[NSEQ*DHD];

// expanded real weights, stored transposed [N'][K'], tf32-rounded
__device__ float g_wq_t [NDEPTH*1024*1024];
__device__ float g_wkv_t[NDEPTH*2048*1024];
__device__ float g_wo_t [NDEPTH*1024*1024];
__device__ float g_w1_t [NDEPTH*4096*1024];
__device__ float g_w2_t [NDEPTH*1024*4096];

// ---------------- helpers ----------------------------------------------------
__device__ __forceinline__ uint32_t f2tf(float x) {
    uint32_t r;
    asm("cvt.rna.tf32.f32 %0, %1;" : "=r"(r) : "f"(x));
    return r;
}
__device__ __forceinline__ float tfr(float x) { return __uint_as_float(f2tf(x)); }

__device__ __forceinline__ void mma8(float* c, const uint32_t* a, const uint32_t* b) {
    asm volatile(
        "mma.sync.aligned.m16n8k8.row.col.f32.tf32.tf32.f32 "
        "{%0,%1,%2,%3}, {%4,%5,%6,%7}, {%8,%9}, {%0,%1,%2,%3};"
        : "+f"(c[0]), "+f"(c[1]), "+f"(c[2]), "+f"(c[3])
        : "r"(a[0]), "r"(a[1]), "r"(a[2]), "r"(a[3]), "r"(b[0]), "r"(b[1]));
}

// ---------------- weight expansion: complex W[K][N] -> real Wt[2N][2K] ------
__global__ void expand_w(const float2* __restrict__ W, float* __restrict__ Wt,
                         int K, int N) {
    int idx = blockIdx.x * 256 + threadIdx.x;
    if (idx >= K * N) return;
    int k = idx % K, n = idx / K;
    float2 w = W[(size_t)k * N + n];
    float r = tfr(w.x), i = tfr(w.y);
    size_t K2 = 2 * (size_t)K;
    *reinterpret_cast<float2*>(&Wt[(2 * (size_t)n)     * K2 + 2 * k]) = make_float2(r, -i);
    *reinterpret_cast<float2*>(&Wt[(2 * (size_t)n + 1) * K2 + 2 * k]) = make_float2(i, r);
}

// ---------------- rope table -------------------------------------------------
__global__ void rope_table() {
    int i = blockIdx.x * 256 + threadIdx.x;
    if (i < NSEQ * DHD) {
        int n = i / DHD, d = i % DHD;
        float invf = powf(10000.0f, -((float)d) / (float)DHD);
        float f = (float)n * invf;
        g_cos[i] = cosf(f);
        g_sin[i] = sinf(f);
    }
}

// ---------------- rmsnorm (optionally tf32-rounds output) -------------------
__global__ void rmsnorm_k(const float2* __restrict__ in,
                          const float2* __restrict__ gamma,
                          float2* __restrict__ out, int tfround) {
    int t = blockIdx.x;
    const float2* xp = in + (size_t)t * DIMC;
    __shared__ float red[256];
    float s = 0.f;
    for (int i = threadIdx.x; i < DIMC; i += 256) {
        float2 v = xp[i];
        s += v.x * v.x + v.y * v.y;
    }
    red[threadIdx.x] = s;
    __syncthreads();
    for (int o = 128; o > 0; o >>= 1) {
        if (threadIdx.x < o) red[threadIdx.x] += red[threadIdx.x + o];
        __syncthreads();
    }
    float inv = rsqrtf(red[0] / (float)DIMC + EPSV);
    for (int i = threadIdx.x; i < DIMC; i += 256) {
        float2 v = xp[i];
        float2 g = gamma[i];
        float xr = v.x * inv, xi = v.y * inv;
        float orr = xr * g.x - xi * g.y;
        float oi  = xr * g.y + xi * g.x;
        if (tfround) { orr = tfr(orr); oi = tfr(oi); }
        out[(size_t)t * DIMC + i] = make_float2(orr, oi);
    }
}

// ---------------- real tf32 GEMM (complex expanded) -------------------------
// C[M][Nc] (complex) from A[M][K2] real x Wt[N2][K2] real (transposed weights)
// block 128x128 (N2 units), BK=16, 8 warps of 64x32.
#define GSTR 20

__global__ __launch_bounds__(256, 2)
void gemm_rx(const float* __restrict__ A, const float* __restrict__ Wt,
             const float2* __restrict__ bias, const float2* __restrict__ res,
             float2* __restrict__ C, int K2, int N2,
             int mode, const float* __restrict__ mb) {
    __shared__ float As[128][GSTR];
    __shared__ float Bs[128][GSTR];

    const int tid  = threadIdx.x;
    const int lane = tid & 31;
    const int warp = tid >> 5;
    const int mbase = (warp >> 2) * 64;   // 0 or 64
    const int nbase = (warp & 3) * 32;    // 0,32,64,96
    const int gr = lane >> 2;
    const int cc = lane & 3;
    const int m0 = blockIdx.y * 128;
    const int n0 = blockIdx.x * 128;
    const int Nc = N2 >> 1;

    float acc[4][4][4];
#pragma unroll
    for (int mt = 0; mt < 4; mt++)
#pragma unroll
        for (int nt = 0; nt < 4; nt++)
#pragma unroll
            for (int e = 0; e < 4; e++) acc[mt][nt][e] = 0.f;

    // tile load indices: float4 f = tid, tid+256; m=f>>2, k4=f&3
    const int lm0 = tid >> 2, lk4 = (tid & 3) * 4;
    const int lm1 = (tid + 256) >> 2;
    const int nkb = K2 / 16;

    float4 aR[2], bR[2];
    aR[0] = *reinterpret_cast<const float4*>(A + (size_t)(m0 + lm0) * K2 + lk4);
    aR[1] = *reinterpret_cast<const float4*>(A + (size_t)(m0 + lm1) * K2 + lk4);
    bR[0] = *reinterpret_cast<const float4*>(Wt + (size_t)(n0 + lm0) * K2 + lk4);
    bR[1] = *reinterpret_cast<const float4*>(Wt + (size_t)(n0 + lm1) * K2 + lk4);
    *reinterpret_cast<float4*>(&As[lm0][lk4]) = aR[0];
    *reinterpret_cast<float4*>(&As[lm1][lk4]) = aR[1];
    *reinterpret_cast<float4*>(&Bs[lm0][lk4]) = bR[0];
    *reinterpret_cast<float4*>(&Bs[lm1][lk4]) = bR[1];
    __syncthreads();

    for (int kb = 0; kb < nkb; kb++) {
        if (kb + 1 < nkb) {
            int k0 = (kb + 1) * 16;
            aR[0] = *reinterpret_cast<const float4*>(A + (size_t)(m0 + lm0) * K2 + k0 + lk4);
            aR[1] = *reinterpret_cast<const float4*>(A + (size_t)(m0 + lm1) * K2 + k0 + lk4);
            bR[0] = *reinterpret_cast<const float4*>(Wt + (size_t)(n0 + lm0) * K2 + k0 + lk4);
            bR[1] = *reinterpret_cast<const float4*>(Wt + (size_t)(n0 + lm1) * K2 + k0 + lk4);
        }

#pragma unroll
        for (int ks = 0; ks < 16; ks += 8) {
            uint32_t a[4][4];
#pragma unroll
            for (int mt = 0; mt < 4; mt++) {
                int r = mbase + mt * 16 + gr;
                a[mt][0] = __float_as_uint(As[r][ks + cc]);
                a[mt][1] = __float_as_uint(As[r + 8][ks + cc]);
                a[mt][2] = __float_as_uint(As[r][ks + cc + 4]);
                a[mt][3] = __float_as_uint(As[r + 8][ks + cc + 4]);
            }
            uint32_t b[4][2];
#pragma unroll
            for (int nt = 0; nt < 4; nt++) {
                int n = nbase + nt * 8 + gr;
                b[nt][0] = __float_as_uint(Bs[n][ks + cc]);
                b[nt][1] = __float_as_uint(Bs[n][ks + cc + 4]);
            }
#pragma unroll
            for (int mt = 0; mt < 4; mt++)
#pragma unroll
                for (int nt = 0; nt < 4; nt++)
                    mma8(acc[mt][nt], a[mt], b[nt]);
        }
        __syncthreads();

        if (kb + 1 < nkb) {
            *reinterpret_cast<float4*>(&As[lm0][lk4]) = aR[0];
            *reinterpret_cast<float4*>(&As[lm1][lk4]) = aR[1];
            *reinterpret_cast<float4*>(&Bs[lm0][lk4]) = bR[0];
            *reinterpret_cast<float4*>(&Bs[lm1][lk4]) = bR[1];
            __syncthreads();
        }
    }

    // epilogue: thread owns complex outputs (row gr / gr+8, complex col nc)
#pragma unroll
    for (int mt = 0; mt < 4; mt++)
#pragma unroll
        for (int nt = 0; nt < 4; nt++) {
            int nc = (n0 + nbase + nt * 8) / 2 + cc;
#pragma unroll
            for (int half = 0; half < 2; half++) {
                int row = m0 + mbase + mt * 16 + gr + half * 8;
                float r = acc[mt][nt][half * 2 + 0];
                float i = acc[mt][nt][half * 2 + 1];
                if (bias) {
                    float2 bb = bias[nc];
                    r += bb.x; i += bb.y;
                }
                if (mode == EP_ROPE || (mode == EP_ROPE_K && nc < DINNER)) {
                    int n = row & (NSEQ - 1);
                    int d = nc & 63;
                    float c = g_cos[n * DHD + d], s = g_sin[n * DHD + d];
                    float t = r * c - i * s; i = r * s + i * c; r = t;
                } else if (mode == EP_NONLIN) {
                    float mbv = *mb;
                    float mag = sqrtf(r * r + i * i);
                    float t = mag + mbv;
                    float cl = t > 0.f ? t * t : 0.f;
                    if (mag > 0.f) { float sc = cl / mag; r *= sc; i *= sc; }
                    else { r = cl; i = 0.f; }
                    r = tfr(r); i = tfr(i);
                }
                if (res) {
                    float2 rr = res[(size_t)row * Nc + nc];
                    r += rr.x; i += rr.y;
                }
                C[(size_t)row * Nc + nc] = make_float2(r, i);
            }
        }
}

// ---------------- tensor-core flash attention -------------------------------
#define ASTR 68
#define VSTR 68
#define FA_SMEM ((5*64*ASTR + 64*VSTR)*4)

__global__ __launch_bounds__(256)
void flash_attn_tc() {
    extern __shared__ uint32_t sm[];
    uint32_t* Qs  = sm;
    uint32_t* Ksr = Qs  + 64*ASTR;
    uint32_t* Ksi = Ksr + 64*ASTR;
    uint32_t* Pa  = Ksi + 64*ASTR;
    uint32_t* Pb  = Pa  + 64*ASTR;
    uint32_t* Vst = Pb  + 64*ASTR;

    const int tid  = threadIdx.x;
    const int lane = tid & 31;
    const int warp = tid >> 5;
    const int half = warp >> 2;
    const int rbase = (warp & 3) * 16;
    const int gr = lane >> 2;
    const int cc = lane & 3;
    const int b = blockIdx.z >> 1;
    const int qpart = blockIdx.z & 1;
    const int h = blockIdx.y;
    const int q0 = blockIdx.x * 64;

    for (int i = tid; i < 64 * 64; i += 256) {
        int r = i >> 6, d = i & 63;
        float2 v = g_q[(size_t)(b * NSEQ + q0 + r) * DINNER + h * DHD + d];
        Qs[r * ASTR + d] = f2tf((qpart ? v.y : v.x) * SCALEV);
    }

    float m0 = -INFINITY, m1 = -INFINITY, l0 = 0.f, l1 = 0.f;
    float oacc[8][4];
#pragma unroll
    for (int nt = 0; nt < 8; nt++)
#pragma unroll
        for (int e = 0; e < 4; e++) oacc[nt][e] = 0.f;

    uint32_t* Ph = half ? Pb : Pa;

    for (int c0 = 0; c0 < NSEQ; c0 += 64) {
        __syncthreads();
        for (int i = tid; i < 64 * 64; i += 256) {
            int key = i >> 6, d = i & 63;
            const float2* p = g_kv + (size_t)(b * NSEQ + c0 + key) * (2 * DINNER) + h * DHD + d;
            float2 kc = p[0];
            float2 vc = p[DINNER];
            Ksr[key * ASTR + d] = f2tf(kc.x);
            Ksi[key * ASTR + d] = f2tf(-kc.y);
            Vst[d * VSTR + key] = f2tf(qpart ? vc.y : vc.x);
        }
        __syncthreads();

        const uint32_t* Kp = half ? Ksi : Ksr;

        float sacc[8][4];
#pragma unroll
        for (int nt = 0; nt < 8; nt++)
#pragma unroll
            for (int e = 0; e < 4; e++) sacc[nt][e] = 0.f;

#pragma unroll
        for (int kk = 0; kk < 64; kk += 8) {
            uint32_t a[4];
            a[0] = Qs[(rbase + gr)     * ASTR + kk + cc];
            a[1] = Qs[(rbase + gr + 8) * ASTR + kk + cc];
            a[2] = Qs[(rbase + gr)     * ASTR + kk + cc + 4];
            a[3] = Qs[(rbase + gr + 8) * ASTR + kk + cc + 4];
#pragma unroll
            for (int nt = 0; nt < 8; nt++) {
                uint32_t bb[2];
                bb[0] = Kp[(nt * 8 + gr) * ASTR + kk + cc];
                bb[1] = Kp[(nt * 8 + gr) * ASTR + kk + cc + 4];
                mma8(sacc[nt], a, bb);
            }
        }

        float rmax0 = -INFINITY, rmax1 = -INFINITY;
#pragma unroll
        for (int nt = 0; nt < 8; nt++) {
            rmax0 = fmaxf(rmax0, fmaxf(sacc[nt][0], sacc[nt][1]));
            rmax1 = fmaxf(rmax1, fmaxf(sacc[nt][2], sacc[nt][3]));
        }
        rmax0 = fmaxf(rmax0, __shfl_xor_sync(0xffffffffu, rmax0, 1));
        rmax0 = fmaxf(rmax0, __shfl_xor_sync(0xffffffffu, rmax0, 2));
        rmax1 = fmaxf(rmax1, __shfl_xor_sync(0xffffffffu, rmax1, 1));
        rmax1 = fmaxf(rmax1, __shfl_xor_sync(0xffffffffu, rmax1, 2));

        float mn0 = fmaxf(m0, rmax0);
        float mn1 = fmaxf(m1, rmax1);
        float corr0 = expf(m0 - mn0);
        float corr1 = expf(m1 - mn1);

        float ps0 = 0.f, ps1 = 0.f;
#pragma unroll
        for (int nt = 0; nt < 8; nt++) {
            float p00 = expf(sacc[nt][0] - mn0);
            float p01 = expf(sacc[nt][1] - mn0);
            float p10 = expf(sacc[nt][2] - mn1);
            float p11 = expf(sacc[nt][3] - mn1);
            ps0 += p00 + p01;
            ps1 += p10 + p11;
            uint2 u0 = make_uint2(f2tf(p00), f2tf(p01));
            uint2 u1 = make_uint2(f2tf(p10), f2tf(p11));
            *reinterpret_cast<uint2*>(&Ph[(rbase + gr)     * ASTR + nt * 8 + 2 * cc]) = u0;
            *reinterpret_cast<uint2*>(&Ph[(rbase + gr + 8) * ASTR + nt * 8 + 2 * cc]) = u1;
        }
        ps0 += __shfl_xor_sync(0xffffffffu, ps0, 1);
        ps0 += __shfl_xor_sync(0xffffffffu, ps0, 2);
        ps1 += __shfl_xor_sync(0xffffffffu, ps1, 1);
        ps1 += __shfl_xor_sync(0xffffffffu, ps1, 2);

        l0 = l0 * corr0 + ps0;
        l1 = l1 * corr1 + ps1;
#pragma unroll
        for (int nt = 0; nt < 8; nt++) {
            oacc[nt][0] *= corr0; oacc[nt][1] *= corr0;
            oacc[nt][2] *= corr1; oacc[nt][3] *= corr1;
        }
        m0 = mn0; m1 = mn1;

#pragma unroll
        for (int kk = 0; kk < 64; kk += 8) {
            uint32_t a[4];
            a[0] = Ph[(rbase + gr)     * ASTR + kk + cc];
            a[1] = Ph[(rbase + gr + 8) * ASTR + kk + cc];
            a[2] = Ph[(rbase + gr)     * ASTR + kk + cc + 4];
            a[3] = Ph[(rbase + gr + 8) * ASTR + kk + cc + 4];
#pragma unroll
            for (int nt = 0; nt < 8; nt++) {
                uint32_t bb[2];
                bb[0] = Vst[(nt * 8 + gr) * VSTR + kk + cc];
                bb[1] = Vst[(nt * 8 + gr) * VSTR + kk + cc + 4];
                mma8(oacc[nt], a, bb);
            }
        }
    }

    float inv0 = 1.f / l0;
    float inv1 = 1.f / l1;
    int r = half + qpart * 2;
    size_t rowb = ((size_t)((r * BBATCH + b) * NHEADS + h) * NSEQ + q0 + rbase);
#pragma unroll
    for (int nt = 0; nt < 8; nt++) {
        int col = nt * 8 + 2 * cc;
        *reinterpret_cast<float2*>(&g_o4[(rowb + gr) * DHD + col]) =
            make_float2(oacc[nt][0] * inv0, oacc[nt][1] * inv0);
        *reinterpret_cast<float2*>(&g_o4[(rowb + gr + 8) * DHD + col]) =
            make_float2(oacc[nt][2] * inv1, oacc[nt][3] * inv1);
    }
}

// combine 4 attention planes -> complex (tf32-rounded: feeds Wo GEMM's A)
__global__ void combine_o() {
    int i = blockIdx.x * 256 + threadIdx.x;
    int d  = i % DHD;
    int hh = (i / DHD) % NHEADS;
    int n  = (i / DINNER) % NSEQ;
    int b  = i / (DINNER * NSEQ);
    size_t idx4 = ((size_t)(b * NHEADS + hh) * NSEQ + n) * DHD + d;
    const size_t plane = (size_t)BBATCH * NHEADS * NSEQ * DHD;
    float rr = g_o4[idx4];
    float ri = g_o4[plane + idx4];
    float ir = g_o4[2 * plane + idx4];
    float ii = g_o4[3 * plane + idx4];
    g_oc[i] = make_float2(tfr(rr - ii), tfr(ri + ir));
}

// ---------------- host orchestration ---------------------------------------
extern "C" void kernel_launch(void* const* d_in, const int* in_sizes, int n_in,
                              void* d_out, int out_size) {
    const float2* x           = (const float2*)d_in[0];
    const float2* gamma_attn  = (const float2*)d_in[1];
    const float2* Wq          = (const float2*)d_in[2];
    const float2* Wkv         = (const float2*)d_in[3];
    const float2* Wo          = (const float2*)d_in[4];
    const float2* gamma_ff    = (const float2*)d_in[5];
    const float2* W1          = (const float2*)d_in[6];
    const float2* b1          = (const float2*)d_in[7];
    const float*  mod_bias    = (const float*)d_in[8];
    const float2* W2          = (const float2*)d_in[9];
    const float2* b2          = (const float2*)d_in[10];
    const float2* gamma_final = (const float2*)d_in[11];

    float2 *px, *ph, *pq, *pkv, *poc, *ph1;
    float *wq_t, *wkv_t, *wo_t, *w1_t, *w2_t;
    cudaGetSymbolAddress((void**)&px,  g_x);
    cudaGetSymbolAddress((void**)&ph,  g_h);
    cudaGetSymbolAddress((void**)&pq,  g_q);
    cudaGetSymbolAddress((void**)&pkv, g_kv);
    cudaGetSymbolAddress((void**)&poc, g_oc);
    cudaGetSymbolAddress((void**)&ph1, g_h1);
    cudaGetSymbolAddress((void**)&wq_t,  g_wq_t);
    cudaGetSymbolAddress((void**)&wkv_t, g_wkv_t);
    cudaGetSymbolAddress((void**)&wo_t,  g_wo_t);
    cudaGetSymbolAddress((void**)&w1_t,  g_w1_t);
    cudaGetSymbolAddress((void**)&w2_t,  g_w2_t);

    cudaFuncSetAttribute(flash_attn_tc,
                         cudaFuncAttributeMaxDynamicSharedMemorySize, FA_SMEM);

    rope_table<<<(NSEQ * DHD + 255) / 256, 256>>>();

    // expand weights (tf32-rounded, transposed)
    for (int l = 0; l < NDEPTH; l++) {
        expand_w<<<(DIMC * DINNER + 255) / 256, 256>>>(
            Wq + (size_t)l * DIMC * DINNER, wq_t + (size_t)l * 1024 * 1024, DIMC, DINNER);
        expand_w<<<(DIMC * 2 * DINNER + 255) / 256, 256>>>(
            Wkv + (size_t)l * DIMC * 2 * DINNER, wkv_t + (size_t)l * 2048 * 1024, DIMC, 2 * DINNER);
        expand_w<<<(DINNER * DIMC + 255) / 256, 256>>>(
            Wo + (size_t)l * DINNER * DIMC, wo_t + (size_t)l * 1024 * 1024, DINNER, DIMC);
        expand_w<<<(DIMC * FFD + 255) / 256, 256>>>(
            W1 + (size_t)l * DIMC * FFD, w1_t + (size_t)l * 4096 * 1024, DIMC, FFD);
        expand_w<<<(FFD * DIMC + 255) / 256, 256>>>(
            W2 + (size_t)l * FFD * DIMC, w2_t + (size_t)l * 1024 * 4096, FFD, DIMC);
    }

    for (int l = 0; l < NDEPTH; l++) {
        const float2* r0 = (l == 0) ? x : px;

        rmsnorm_k<<<MTOK, 256>>>(r0, gamma_attn + (size_t)l * DIMC, ph, 1);
        gemm_rx<<<dim3(1024 / 128, MTOK / 128), 256>>>(
            (const float*)ph, wq_t + (size_t)l * 1024 * 1024, nullptr, nullptr, pq,
            1024, 1024, EP_ROPE, nullptr);
        gemm_rx<<<dim3(2048 / 128, MTOK / 128), 256>>>(
            (const float*)ph, wkv_t + (size_t)l * 2048 * 1024, nullptr, nullptr, pkv,
            1024, 2048, EP_ROPE_K, nullptr);
        flash_attn_tc<<<dim3(NSEQ / 64, NHEADS, BBATCH * 2), 256, FA_SMEM>>>();
        combine_o<<<BBATCH * NSEQ * DINNER / 256, 256>>>();
        gemm_rx<<<dim3(1024 / 128, MTOK / 128), 256>>>(
            (const float*)poc, wo_t + (size_t)l * 1024 * 1024, nullptr, r0, px,
            1024, 1024, EP_NONE, nullptr);

        rmsnorm_k<<<MTOK, 256>>>(px, gamma_ff + (size_t)l * DIMC, ph, 1);
        gemm_rx<<<dim3(4096 / 128, MTOK / 128), 256>>>(
            (const float*)ph, w1_t + (size_t)l * 4096 * 1024, b1 + (size_t)l * FFD, nullptr, ph1,
            1024, 4096, EP_NONLIN, mod_bias + l);
        gemm_rx<<<dim3(1024 / 128, MTOK / 128), 256>>>(
            (const float*)ph1, w2_t + (size_t)l * 1024 * 4096, b2 + (size_t)l * DIMC, px, px,
            4096, 1024, EP_NONE, nullptr);
    }

    rmsnorm_k<<<MTOK, 256>>>(px, gamma_final, (float2*)d_out, 0);
}